// round 16
// baseline (speedup 1.0000x reference)
#include <cuda_runtime.h>
#include <cuda_fp16.h>
#include <cstdint>

// ---------------------------------------------------------------------------
// FeedBack LSTM via mma.sync fp16 (baseline PTX; sm_103 target, no 'a' feats).
// R16: per-tile producer/consumer dataflow replaces the per-step group
// barrier. Monotonic counters per (group, tile): produce-flag (consumer at
// step t waits >= 8t) and consume-ack (producer waits >= 8(t-1) before
// overwriting the double buffer). Steps pipeline at tile granularity.
// Persistent kernel, c in SMEM, single-term fp16 GEMM (z = Ah·Bh), folded AR
// weights, MUFU activations, one pred_all at the end.
// B=16384, T=48, F=4, UNITS=256 (z width 1024), OUT_STEPS=24.
// ---------------------------------------------------------------------------

namespace {
constexpr int BATCH = 16384;
constexpr int SEQ_T = 48;
constexpr int FDIM  = 4;
constexpr int NU    = 256;
constexpr int NOUT  = 24;
constexpr int Z4    = 1024;

constexpr int THREADS = 256;   // 8 warps: 2 m-warps x 4 n-warps (warp 32x32)
constexpr int NM16 = BATCH / 16;        // 1024 m16 blocks
constexpr int NKC  = NU / 16;           // 16 k16 chunks
constexpr int NT8  = Z4 / 8;            // 128 n8 tiles
constexpr int NCTA = 296;               // exactly 2 CTAs per SM (148 SMs)
constexpr int NGRP = 37;                // row groups (8 CTAs each)
constexpr int NTILE_MAX = 7;            // ceil(256/37)
constexpr int NSTEPS = SEQ_T + NOUT - 1;  // 71
constexpr long BUFQ = (long)NM16 * NKC * 32;
constexpr long HSLOT = (long)BATCH * NU;
constexpr int CSMEM_BYTES = NTILE_MAX * 8 * 256 * 4;   // 57344
constexpr int BARSTRIDE = 32;           // ints; 128B padding per counter
}

// ---------------- device state (allocation-free) ----------------
// A fragments (fp16 hi): [buf][m16blk(1024)][kchunk(16)][lane(32)] : uint4
__device__ __align__(16) uint4 g_a4h[2 * NM16 * NKC * 32];
// B fragments (fp16): [ntile(128)][kchunk(16)][lane(32)] : uint2 = b0,b1
__device__ __align__(16) uint2 g_b2w[NT8 * NKC * 32];    // warmup: Wh
__device__ __align__(16) uint2 g_b2ar[NT8 * NKC * 32];   // AR: Wh + Wd@Wx
// permuted Wx / biases (fp32)
__device__ float g_wxp[FDIM * Z4];
__device__ float g_bp[Z4];       // permuted b
__device__ float g_bpar[Z4];     // permuted b + bd@Wx
// per-output-step h slots (slot 0 = warmup final; slot s = AR step s)
__device__ float g_hall[NOUT * BATCH * NU];
// per-(group,tile) dataflow counters, monotonic within a launch, reset at end
__device__ volatile unsigned int g_flag[NGRP * NTILE_MAX * BARSTRIDE];
__device__ volatile unsigned int g_ack[NGRP * NTILE_MAX * BARSTRIDE];
// final group barrier (gen monotonic across replays; count self-resets)
__device__ volatile unsigned int g_bar_gen[NGRP * BARSTRIDE];
__device__ unsigned int g_bar_count[NGRP * BARSTRIDE];

// ---------------- helpers ----------------
__device__ __forceinline__ void mma16816(float* d, const uint32_t* a,
                                         const uint32_t* b) {
    asm volatile(
        "mma.sync.aligned.m16n8k16.row.col.f32.f16.f16.f32 "
        "{%0,%1,%2,%3}, {%4,%5,%6,%7}, {%8,%9}, {%0,%1,%2,%3};"
        : "+f"(d[0]), "+f"(d[1]), "+f"(d[2]), "+f"(d[3])
        : "r"(a[0]), "r"(a[1]), "r"(a[2]), "r"(a[3]), "r"(b[0]), "r"(b[1]));
}
__device__ __forceinline__ float tanh_fast(float x) {
    float y;
    asm("tanh.approx.f32 %0, %1;" : "=f"(y) : "f"(x));
    return y;
}
__device__ __forceinline__ float sigmoid_fast(float x) {
    return fmaf(0.5f, tanh_fast(0.5f * x), 0.5f);
}
__device__ __forceinline__ uint32_t pack_h2(float a, float b) {
    __half2 h = __floats2half2_rn(a, b);
    return *reinterpret_cast<uint32_t*>(&h);
}

// final 8-CTA group barrier (group = ci)
__device__ __forceinline__ void group_barrier(int gid) {
    __syncthreads();
    if (threadIdx.x == 0) {
        const int slot = gid * BARSTRIDE;
        __threadfence();
        unsigned int gen = g_bar_gen[slot];
        if (atomicAdd(&g_bar_count[slot], 1u) == 7u) {
            g_bar_count[slot] = 0;
            __threadfence();
            g_bar_gen[slot] = gen + 1;
        } else {
            while (g_bar_gen[slot] == gen) { __nanosleep(32); }
            __threadfence();
        }
    }
    __syncthreads();
}

// ---------------- prep kernels ----------------
// Permuted z-col p: nt=p>>7, loc=p&127; wn=loc>>5, g=(loc>>3)&3, ul=loc&7;
// unit u = nt*32 + wn*8 + ul; original col oc = g*256 + u.
// ar=0: W = Wh ; ar=1: W = Wh + Wd@Wx (feedback folded).
__global__ void prep_b2(const float* __restrict__ Wh,
                        const float* __restrict__ Wd,
                        const float* __restrict__ Wx,
                        int ar, uint2* __restrict__ dst) {
    int idx = blockIdx.x * 256 + threadIdx.x;   // 65536 = 128 nt8 x 16 kc x 32
    int lane = idx & 31;
    int kc   = (idx >> 5) & 15;
    int ntile = idx >> 9;
    int q = lane >> 2, s = lane & 3;
    int p = ntile * 8 + q;                      // permuted z-col (n of frag)
    int nt = p >> 7, loc = p & 127;
    int wn = loc >> 5, g = (loc >> 3) & 3, ul = loc & 7;
    int oc = g * 256 + nt * 32 + wn * 8 + ul;   // original z column
    int k0 = kc * 16 + 2 * s;
    float v[4];
    const int kk[4] = {k0, k0 + 1, k0 + 8, k0 + 9};
    #pragma unroll
    for (int j = 0; j < 4; j++) {
        float w = Wh[kk[j] * Z4 + oc];
        if (ar) {
            #pragma unroll
            for (int f = 0; f < FDIM; f++)
                w = fmaf(Wd[kk[j] * FDIM + f], Wx[f * Z4 + oc], w);
        }
        v[j] = w;
    }
    uint2 r;
    r.x = pack_h2(v[0], v[1]);  // b0
    r.y = pack_h2(v[2], v[3]);  // b1
    dst[idx] = r;
}

__global__ void prep_wxb(const float* __restrict__ Wx,
                         const float* __restrict__ b,
                         const float* __restrict__ bd) {
    int p = threadIdx.x;                        // 0..1023
    int nt = p >> 7, loc = p & 127;
    int wn = loc >> 5, g = (loc >> 3) & 3, ul = loc & 7;
    int oc = g * 256 + nt * 32 + wn * 8 + ul;
    float bb = b[oc];
    g_bp[p] = bb;
    float ba = bb;
    #pragma unroll
    for (int f = 0; f < FDIM; f++) {
        g_wxp[f * Z4 + p] = Wx[f * Z4 + oc];
        ba = fmaf(bd[f], Wx[f * Z4 + oc], ba);
    }
    g_bpar[p] = ba;
}

// ---------------- persistent all-steps kernel ----------------
__global__ void __launch_bounds__(THREADS, 2)
lstm_persist(const float* __restrict__ x)
{
    extern __shared__ float c_s[];            // [NTILE_MAX][8][256]
    __shared__ float wx_s[4 * 128];
    __shared__ float bpw_s[128];
    __shared__ float bpa_s[128];

    const int tid  = threadIdx.x;
    const int lane = tid & 31;
    const int wid  = tid >> 5;
    const int wm   = wid & 1;        // m-warp: rows wm*32..+32 (of 64)
    const int wn   = wid >> 1;       // n-warp: permuted cols wn*32..+32
    const int ct   = blockIdx.x;     // 0..295
    const int nt   = ct & 7;         // fixed per CTA -> B reuse
    const int ci   = ct >> 3;        // 0..36 = row group id; rt = ci + 37*j
    const int fbase = ci * NTILE_MAX * BARSTRIDE;

    for (int i = tid; i < 4 * 128; i += THREADS) {
        int f = i >> 7, j = i & 127;
        wx_s[i] = g_wxp[f * Z4 + nt * 128 + j];
    }
    if (tid < 128) {
        bpw_s[tid] = g_bp[nt * 128 + tid];
        bpa_s[tid] = g_bpar[nt * 128 + tid];
    }
    __syncthreads();

    const int q  = lane >> 2;
    const int s4 = lane & 3;
    const int kcs = nt * 2 + (wn >> 1);     // kchunk of this warp's units
    const int slotbase = (wn & 1) * 2;      // a0a1 (k<8) or a2a3 (k>=8)

    for (int t = 0; t < NSTEPS; t++) {
        const int warm = (t < SEQ_T);
        const int produce = (t < NSTEPS - 1);
        const uint2* __restrict__ b2 = warm ? g_b2w : g_b2ar;
        const float* bias = warm ? bpw_s : bpa_s;
        const uint4* __restrict__ a_in = g_a4h + ((t + 1) & 1) * BUFQ;
        uint4* __restrict__ a_out = g_a4h + (t & 1) * BUFQ;
        uint32_t* ah32 = reinterpret_cast<uint32_t*>(a_out);
        float* h_slot = nullptr;
        if (t == SEQ_T - 1)      h_slot = g_hall;
        else if (t >= SEQ_T)     h_slot = g_hall + (long)(t - SEQ_T + 1) * HSLOT;
        const float* xt = x + t * FDIM;

        int jt = 0;
        for (int rt = ci; rt < 256; rt += NGRP, jt++) {
            const int fslot = fbase + jt * BARSTRIDE;

            // accumulators d[mi][gate][frag]
            float d[2][4][4];
            #pragma unroll
            for (int mi = 0; mi < 2; mi++)
                #pragma unroll
                for (int g = 0; g < 4; g++)
                    #pragma unroll
                    for (int r = 0; r < 4; r++)
                        d[mi][g][r] = 0.0f;

            if (t > 0) {
                // consumer wait: tile jt produced by all 8 CTAs at step t-1
                if (tid == 0) {
                    const unsigned tgt = 8u * (unsigned)t;
                    while (g_flag[fslot] < tgt) { __nanosleep(32); }
                    __threadfence();           // acquire producers' stores
                }
                __syncthreads();

                const int aBase = ((rt * 4 + wm * 2) * 16) * 32 + lane;
                const int bBase = ((nt * 16 + wn * 4) * 16) * 32 + lane;

                uint4 Ah[2][2];
                uint2 Bq[2][4];
                #pragma unroll
                for (int mi = 0; mi < 2; mi++)
                    Ah[0][mi] = __ldcg(&a_in[aBase + mi * 512]);
                #pragma unroll
                for (int g = 0; g < 4; g++)
                    Bq[0][g] = b2[bBase + g * 512];

                #pragma unroll
                for (int kc = 0; kc < NKC; kc++) {
                    const int cur = kc & 1, nx = cur ^ 1;
                    if (kc < NKC - 1) {
                        const int ko = (kc + 1) * 32;
                        #pragma unroll
                        for (int mi = 0; mi < 2; mi++)
                            Ah[nx][mi] = __ldcg(&a_in[aBase + mi * 512 + ko]);
                        #pragma unroll
                        for (int g = 0; g < 4; g++)
                            Bq[nx][g] = b2[bBase + g * 512 + ko];
                    }
                    #pragma unroll
                    for (int mi = 0; mi < 2; mi++) {
                        const uint32_t* ah =
                            reinterpret_cast<const uint32_t*>(&Ah[cur][mi]);
                        #pragma unroll
                        for (int g = 0; g < 4; g++) {
                            const uint32_t bh[2] = {Bq[cur][g].x, Bq[cur][g].y};
                            mma16816(d[mi][g], ah, bh);
                        }
                    }
                }

                // consume-ack: all reads of this tile's buffer are complete
                __syncthreads();
                if (tid == 0)
                    atomicAdd((unsigned int*)&g_ack[fslot], 1u);
            }

            // producer WAR wait: buffer (t&1) of tile jt (written at t-2)
            // must be fully consumed (step t-1) before overwrite.
            if (produce && t >= 2) {
                if (tid == 0) {
                    const unsigned tgt = 8u * (unsigned)(t - 1);
                    while (g_ack[fslot] < tgt) { __nanosleep(32); }
                }
                __syncthreads();
            }

            // ---- epilogue: z -> gates -> c,h; A-frag (+ fp32 h) ----
            float* cslot = c_s + (jt * 8) * 256 + tid;   // [val][256] stride
            #pragma unroll
            for (int mi = 0; mi < 2; mi++) {
                float hn[2][2];                      // [rh][par]
                #pragma unroll
                for (int rh = 0; rh < 2; rh++) {
                    const int row = rt * 64 + wm * 32 + mi * 16 + q + rh * 8;
                    float4 xv = make_float4(0.f, 0.f, 0.f, 0.f);
                    if (warm)
                        xv = *reinterpret_cast<const float4*>(
                            &xt[(long)row * (SEQ_T * FDIM)]);
                    float hn2[2];
                    #pragma unroll
                    for (int par = 0; par < 2; par++) {
                        const int vofs = (mi * 4 + rh * 2 + par) * 256;
                        const float cold = (t == 0) ? 0.0f : cslot[vofs];
                        float z[4];
                        #pragma unroll
                        for (int g = 0; g < 4; g++) {
                            const int nl = wn * 32 + g * 8 + s4 * 2 + par;
                            float zz = bias[nl] + d[mi][g][rh * 2 + par];
                            if (warm) {
                                zz = fmaf(xv.x, wx_s[nl],       zz);
                                zz = fmaf(xv.y, wx_s[128 + nl], zz);
                                zz = fmaf(xv.z, wx_s[256 + nl], zz);
                                zz = fmaf(xv.w, wx_s[384 + nl], zz);
                            }
                            z[g] = zz;
                        }
                        const float ig = sigmoid_fast(z[0]);
                        const float fg = sigmoid_fast(z[1]);
                        const float gg = tanh_fast(z[2]);
                        const float og = sigmoid_fast(z[3]);
                        const float cn = fg * cold + ig * gg;
                        const float hv = og * tanh_fast(cn);
                        cslot[vofs] = cn;
                        hn2[par] = hv;
                        hn[rh][par] = hv;
                    }
                    if (h_slot) {
                        const int hi = row * NU + nt * 32 + wn * 8 + s4 * 2;
                        *reinterpret_cast<float2*>(&h_slot[hi]) =
                            make_float2(hn2[0], hn2[1]);
                    }
                }
                // A-fragment store (identity map); skipped on final step
                if (produce) {
                    const int m16blk = rt * 4 + wm * 2 + mi;
                    const int fb = ((m16blk * 16 + kcs) * 32 + lane) * 4
                                   + slotbase;
                    uint2 fh;
                    fh.x = pack_h2(hn[0][0], hn[0][1]);
                    fh.y = pack_h2(hn[1][0], hn[1][1]);
                    *reinterpret_cast<uint2*>(&ah32[fb]) = fh;
                }
            }

            // produce arrive: this CTA's slice of tile jt is globally visible
            if (produce) {
                __threadfence();               // release A-frag stores
                __syncthreads();               // all threads fenced
                if (tid == 0)
                    atomicAdd((unsigned int*)&g_flag[fslot], 1u);
            }
        }
    }

    // drain group, then reset this group's dataflow counters for next replay
    group_barrier(ci);
    if (nt == 0 && tid < NTILE_MAX) {
        g_flag[fbase + tid * BARSTRIDE] = 0u;
        g_ack[fbase + tid * BARSTRIDE] = 0u;
    }
}

// All 24 predictions in one launch: out[row, s, :] = hall[s, row, :]@Wd + bd
__global__ void pred_all(const float* __restrict__ hall,
                         const float* __restrict__ Wd,
                         const float* __restrict__ bd,
                         float* __restrict__ out)
{
    const int gwarp = (blockIdx.x * blockDim.x + threadIdx.x) >> 5;
    const int lane  = threadIdx.x & 31;
    if (gwarp >= NOUT * BATCH) return;
    const int s   = gwarp >> 14;          // / BATCH
    const int row = gwarp & (BATCH - 1);

    const float* hrow = hall + ((long)s * BATCH + row) * NU;
    float a0 = 0.f, a1 = 0.f, a2 = 0.f, a3 = 0.f;
    #pragma unroll
    for (int k = lane; k < NU; k += 32) {
        float hv = hrow[k];
        float4 wv = *reinterpret_cast<const float4*>(&Wd[k * 4]);
        a0 = fmaf(hv, wv.x, a0);
        a1 = fmaf(hv, wv.y, a1);
        a2 = fmaf(hv, wv.z, a2);
        a3 = fmaf(hv, wv.w, a3);
    }
    #pragma unroll
    for (int off = 16; off > 0; off >>= 1) {
        a0 += __shfl_down_sync(0xffffffffu, a0, off);
        a1 += __shfl_down_sync(0xffffffffu, a1, off);
        a2 += __shfl_down_sync(0xffffffffu, a2, off);
        a3 += __shfl_down_sync(0xffffffffu, a3, off);
    }
    if (lane == 0) {
        float4 r = make_float4(a0 + bd[0], a1 + bd[1], a2 + bd[2], a3 + bd[3]);
        *reinterpret_cast<float4*>(&out[((long)row * NOUT + s) * FDIM]) = r;
    }
}

extern "C" void kernel_launch(void* const* d_in, const int* in_sizes, int n_in,
                              void* d_out, int out_size)
{
    const float* x  = (const float*)d_in[0];
    const float* Wx = (const float*)d_in[1];
    const float* Wh = (const float*)d_in[2];
    const float* b  = (const float*)d_in[3];
    const float* Wd = (const float*)d_in[4];
    const float* bd = (const float*)d_in[5];
    float* out = (float*)d_out;

    uint2 *b2w = nullptr, *b2ar = nullptr;
    float* hall = nullptr;
    cudaGetSymbolAddress((void**)&b2w, g_b2w);
    cudaGetSymbolAddress((void**)&b2ar, g_b2ar);
    cudaGetSymbolAddress((void**)&hall, g_hall);

    cudaFuncSetAttribute(lstm_persist,
                         cudaFuncAttributeMaxDynamicSharedMemorySize,
                         CSMEM_BYTES);

    // weight prep (re-run every replay -> deterministic)
    prep_b2<<<256, 256>>>(Wh, Wd, Wx, 0, b2w);
    prep_b2<<<256, 256>>>(Wh, Wd, Wx, 1, b2ar);
    prep_wxb<<<1, 1024>>>(Wx, b, bd);

    // all 71 recurrent steps in one persistent kernel
    lstm_persist<<<NCTA, THREADS, CSMEM_BYTES>>>(x);

    // all predictions in one shot
    const int pblocks = (NOUT * BATCH * 32) / 256;
    pred_all<<<pblocks, 256>>>(hall, Wd, bd, out);
}